// round 15
// baseline (speedup 1.0000x reference)
#include <cuda_runtime.h>
#include <cuda_bf16.h>

// Sparsemax over rows: x, mask are [8192, 4096] fp32; out fp32 same shape.
// z = (mask ? x : NEG_BIG) * 2 ; tau solves sum(relu(z - tau)) = 1 ;
// out = relu(z - tau)  (mask multiply implied: masked z is hugely negative).
//
// R15 = R14's slim warp-local Newton (CAP 64: 2 cand regs/lane, ballot count,
// 5-shuffle sum) + R11's ballot gather into PER-WARP 8-slot segments
// (2 __syncthreads per row, no prefix scan, no cross-warp base loop).
// Lanes holding >=2 candidates or warp counts >8 (data-rare) flag overflow
// -> proven block-Newton fallback (block-uniform decision).

#define ROWS 8192
#define COLS 4096
#define THREADS 256
#define NWARPS (THREADS / 32)
#define ELEMS (COLS / THREADS)   // 16 floats per thread
#define VEC (ELEMS / 4)          // 4 float4 per thread
#define WCAP 8                   // candidate slots per warp
#define CAP (NWARPS * WCAP)      // 64 total (2 per lane)

__global__ __launch_bounds__(THREADS, 5)
void sparsemax_kernel(const float* __restrict__ x,
                      const float* __restrict__ m,
                      float* __restrict__ out) {
    const int row = blockIdx.x;
    const int t   = threadIdx.x;
    const int lane = t & 31;
    const int wid  = t >> 5;

    const float4* __restrict__ xr = reinterpret_cast<const float4*>(x + (size_t)row * COLS);
    const float4* __restrict__ mr = reinterpret_cast<const float4*>(m + (size_t)row * COLS);
    float4* __restrict__ orow     = reinterpret_cast<float4*>(out + (size_t)row * COLS);

    __shared__ float shmax[NWARPS];
    __shared__ int   wovf[NWARPS];    // warp overflow flags
    __shared__ float cand[CAP];
    __shared__ float fs[2][NWARPS];   // fallback double-buffer (sum)
    __shared__ int   fc[2][NWARPS];   // fallback double-buffer (count)

    // ---- Front-batch ALL loads (8 x LDG.128 in flight per thread) ----
    float4 xv[VEC];
    float4 mv[VEC];
#pragma unroll
    for (int v = 0; v < VEC; v++) xv[v] = xr[t + v * THREADS];
#pragma unroll
    for (int v = 0; v < VEC; v++) mv[v] = mr[t + v * THREADS];

    // Pre-initialize this warp's candidate segment (ordered by barrier 1).
    if (lane < WCAP) cand[wid * WCAP + lane] = -3.0e38f;

    // ---- Apply mask + temperature, track local max ----
    float z[ELEMS];
    float vmax = -3.0e38f;
    const float NEGZ = -9999999.9f * 2.0f;  // masked value after temperature
#pragma unroll
    for (int v = 0; v < VEC; v++) {
        float z0 = (mv[v].x != 0.0f) ? (xv[v].x * 2.0f) : NEGZ;
        float z1 = (mv[v].y != 0.0f) ? (xv[v].y * 2.0f) : NEGZ;
        float z2 = (mv[v].z != 0.0f) ? (xv[v].z * 2.0f) : NEGZ;
        float z3 = (mv[v].w != 0.0f) ? (xv[v].w * 2.0f) : NEGZ;
        z[v * 4 + 0] = z0;
        z[v * 4 + 1] = z1;
        z[v * 4 + 2] = z2;
        z[v * 4 + 3] = z3;
        vmax = fmaxf(vmax, fmaxf(fmaxf(z0, z1), fmaxf(z2, z3)));
    }

    // ---- Block max reduction ----
#pragma unroll
    for (int o = 16; o > 0; o >>= 1)
        vmax = fmaxf(vmax, __shfl_xor_sync(0xFFFFFFFFu, vmax, o));
    if (lane == 0) shmax[wid] = vmax;
    __syncthreads();                       // barrier 1
    float zmax = -3.0e38f;
#pragma unroll
    for (int i = 0; i < NWARPS; i++) zmax = fmaxf(zmax, shmax[i]);

    const float T0 = zmax - 1.0f;

    // ---- Ballot gather into this warp's private segment ----
    int   lc = 0;
    float cv = -3.0e38f;
#pragma unroll
    for (int e = 0; e < ELEMS; e++) {
        if (z[e] > T0) { lc++; cv = z[e]; }
    }
    const unsigned has   = __ballot_sync(0xFFFFFFFFu, lc > 0);
    const unsigned multi = __ballot_sync(0xFFFFFFFFu, lc > 1);
    if (lc == 1) {
        int slot = __popc(has & ((1u << lane) - 1u));
        if (slot < WCAP) cand[wid * WCAP + slot] = cv;
    }
    if (lane == 0)
        wovf[wid] = (multi != 0u || __popc(has) > WCAP) ? 1 : 0;
    __syncthreads();                       // barrier 2 (last barrier)

    bool ovf = false;
#pragma unroll
    for (int i = 0; i < NWARPS; i++) ovf |= (wovf[i] != 0);

    float tau;
    if (!ovf) {
        // ---- Slim warp-local Newton (every warp redundantly; same tau) ----
        float c0 = cand[lane +  0];
        float c1 = cand[lane + 32];

        float T = T0;
#pragma unroll 1
        for (int it = 0; it < 32; ++it) {
            float d0 = c0 - T;
            float d1 = c1 - T;
            float s = 0.0f;
            if (d0 > 0.0f) s += d0;
            if (d1 > 0.0f) s += d1;
            int c = __popc(__ballot_sync(0xFFFFFFFFu, d0 > 0.0f))
                  + __popc(__ballot_sync(0xFFFFFFFFu, d1 > 0.0f));
#pragma unroll
            for (int o = 16; o > 0; o >>= 1)
                s += __shfl_xor_sync(0xFFFFFFFFu, s, o);
            if (c == 0) break;             // can't happen (zmax is a candidate)
            float delta = __fdividef(s - 1.0f, (float)c);
            T += delta;
            if (fabsf(delta) < 1e-6f) break;
        }
        tau = T;
    } else {
        // ---- Fallback: proven block-Newton (block-uniform branch) ----
        float T = T0;
#pragma unroll 1
        for (int it = 0; it < 32; ++it) {
            const int b = it & 1;
            float s = 0.0f;
            int   c = 0;
#pragma unroll
            for (int e = 0; e < ELEMS; e++) {
                float d = z[e] - T;
                if (d > 0.0f) { s += d; c += 1; }
            }
#pragma unroll
            for (int o = 16; o > 0; o >>= 1) {
                s += __shfl_xor_sync(0xFFFFFFFFu, s, o);
                c += __shfl_xor_sync(0xFFFFFFFFu, c, o);
            }
            if (lane == 0) { fs[b][wid] = s; fc[b][wid] = c; }
            __syncthreads();
            float S = 0.0f;
            int   C = 0;
#pragma unroll
            for (int i = 0; i < NWARPS; i++) { S += fs[b][i]; C += fc[b][i]; }

            if (C == 0) break;
            float delta = __fdividef(S - 1.0f, (float)C);
            T += delta;
            if (fabsf(delta) < 1e-6f) break;
        }
        tau = T;
    }

    // ---- Output: relu(z - tau). Masked entries are ~-2e7, relu -> 0. ----
#pragma unroll
    for (int v = 0; v < VEC; v++) {
        float4 ov;
        ov.x = fmaxf(0.0f, z[v * 4 + 0] - tau);
        ov.y = fmaxf(0.0f, z[v * 4 + 1] - tau);
        ov.z = fmaxf(0.0f, z[v * 4 + 2] - tau);
        ov.w = fmaxf(0.0f, z[v * 4 + 3] - tau);
        orow[t + v * THREADS] = ov;
    }
}

extern "C" void kernel_launch(void* const* d_in, const int* in_sizes, int n_in,
                              void* d_out, int out_size) {
    const float* x = (const float*)d_in[0];
    const float* m = (const float*)d_in[1];
    float* out = (float*)d_out;
    sparsemax_kernel<<<ROWS, THREADS>>>(x, m, out);
}